// round 14
// baseline (speedup 1.0000x reference)
#include <cuda_runtime.h>
#include <cuda_bf16.h>
#include <cuda_fp8.h>
#include <math.h>
#include <cstdint>
#include <cstddef>

// Problem constants
#define B_    16
#define NT_   64
#define T_    8
#define D_    25088
#define C_    1000
#define M_    (B_ * NT_)   // 1024
#define NPAD  1024
#define K_    D_

// FP8 scaling
#define SCALE_A  64.0f
#define SCALE_W  2048.0f
#define INV_SCALE (1.0f / (SCALE_A * SCALE_W))

// GEMM tiling (fp8 mma.sync m16n8k32) + bulk-copy pipeline
#define BM     128
#define BN     128
#define BKK    128             // fp8 elems (bytes) per K-chunk
#define STAGES 3
#define SPLITS 7
#define NKC    (K_ / BKK)      // 196 chunks total
#define NIT    (NKC / SPLITS)  // 28 chunks per split
#define SEGW   896             // words (float4) per row per segment = 28 chunks
#define BLK    16384           // one [128 rows x 128 B] block
#define STAGE_BYTES (2 * BLK)
#define SMEM_DATA   1024
#define SMEM_TOTAL  (SMEM_DATA + STAGES * STAGE_BYTES)   // 99328

#define PREP_CTAS 592
#define NJOBS     2048         // 1024 pool rows + 1024 W rows

// ---------------- scratch (blocked, pre-swizzled fp8) ----------------
__device__ __align__(1024) uint8_t g_AB[(size_t)(M_ / 128) * NKC * BLK];
__device__ __align__(1024) uint8_t g_WB[(size_t)(NPAD / 128) * NKC * BLK];
__device__ float g_part[(size_t)SPLITS * M_ * NPAD];
__device__ float g_row_nll[M_];
__device__ int   g_row_valid[M_];
__device__ int   g_flags[8];   // [0..6] segment-done counters, [7] nll done count

__device__ __forceinline__ uint8_t to_e4m3(float v) {
    return (uint8_t)__nv_cvt_float_to_fp8(v, __NV_SATFINITE, __NV_E4M3);
}

// ---------------- kernel 1: persistent prep, 7 K-segments, flags ----------------
__global__ __launch_bounds__(256) void prep_kernel(const float* __restrict__ feats,
                                                   const int* __restrict__ lens,
                                                   const float* __restrict__ W) {
#if __CUDA_ARCH__ >= 900
    if (threadIdx.x == 0) cudaTriggerProgrammaticLaunchCompletion();
#endif
    for (int seg = 0; seg < SPLITS; ++seg) {
        const int wbeg = seg * SEGW;
        const int wend = wbeg + SEGW;
        for (int job = blockIdx.x; job < NJOBS; job += PREP_CTAS) {
            if (job < M_) {
                const int m = job;
                const int b = m / NT_;
                const int len = lens[b];
                const float inv = SCALE_A / (float)len;
                const float4* base = (const float4*)(feats + (size_t)m * T_ * D_);
                const int row = m & 127;
                const int mt  = m >> 7;
                const uint32_t rkey = (uint32_t)((row & 7) << 4);
                uint8_t* tile0 = g_AB + (size_t)mt * NKC * BLK;

                for (int i = wbeg + threadIdx.x; i < wend; i += blockDim.x) {
                    float4 acc = make_float4(0.f, 0.f, 0.f, 0.f);
                    #pragma unroll
                    for (int t = 0; t < T_; ++t) {
                        if (t < len) {
                            float4 v = base[(size_t)t * (D_ / 4) + i];
                            acc.x += v.x; acc.y += v.y; acc.z += v.z; acc.w += v.w;
                        }
                    }
                    uchar4 o;
                    o.x = to_e4m3(acc.x * inv);
                    o.y = to_e4m3(acc.y * inv);
                    o.z = to_e4m3(acc.z * inv);
                    o.w = to_e4m3(acc.w * inv);
                    const int kc  = i >> 5;
                    const int bby = (i & 31) * 4;
                    uint8_t* dst = tile0 + (size_t)kc * BLK + (row << 7) + ((uint32_t)bby ^ rkey);
                    *(uchar4*)dst = o;
                }
            } else {
                const int n = job - M_;        // 0..1023 incl. zero pad rows
                const int row = n & 127;
                const int nt  = n >> 7;
                const uint32_t rkey = (uint32_t)((row & 7) << 4);
                uint8_t* tile0 = g_WB + (size_t)nt * NKC * BLK;
                const int valid = (n < C_);
                const float4* src = (const float4*)(W + (size_t)(valid ? n : 0) * K_);

                for (int i = wbeg + threadIdx.x; i < wend; i += blockDim.x) {
                    uchar4 o = make_uchar4(0, 0, 0, 0);
                    if (valid) {
                        float4 v = src[i];
                        o.x = to_e4m3(v.x * SCALE_W);
                        o.y = to_e4m3(v.y * SCALE_W);
                        o.z = to_e4m3(v.z * SCALE_W);
                        o.w = to_e4m3(v.w * SCALE_W);
                    }
                    const int kc  = i >> 5;
                    const int bby = (i & 31) * 4;
                    uint8_t* dst = tile0 + (size_t)kc * BLK + (row << 7) + ((uint32_t)bby ^ rkey);
                    *(uchar4*)dst = o;
                }
            }
        }
        __syncthreads();
        if (threadIdx.x == 0) {
            __threadfence();
            atomicAdd(&g_flags[seg], 1);
        }
    }
}

// ---------------- bulk copy + mbarrier helpers ----------------
__device__ __forceinline__ void bulk_ld(uint32_t smem_dst, const void* gsrc,
                                        uint32_t bytes, uint32_t mbar) {
    asm volatile(
        "cp.async.bulk.shared::cluster.global.mbarrier::complete_tx::bytes [%0], [%1], %2, [%3];"
        :: "r"(smem_dst), "l"(gsrc), "r"(bytes), "r"(mbar) : "memory");
}
__device__ __forceinline__ void mbar_init(uint32_t mbar, uint32_t cnt) {
    asm volatile("mbarrier.init.shared.b64 [%0], %1;" :: "r"(mbar), "r"(cnt) : "memory");
}
__device__ __forceinline__ void mbar_expect_tx(uint32_t mbar, uint32_t bytes) {
    asm volatile("mbarrier.arrive.expect_tx.shared.b64 _, [%0], %1;"
                 :: "r"(mbar), "r"(bytes) : "memory");
}
__device__ __forceinline__ void mbar_wait(uint32_t mbar, uint32_t parity) {
    asm volatile(
        "{\n\t.reg .pred P1;\n\t"
        "WL_%=:\n\t"
        "mbarrier.try_wait.parity.acquire.cta.shared::cta.b64 P1, [%0], %1, 0x989680;\n\t"
        "@P1 bra.uni WD_%=;\n\t"
        "bra.uni WL_%=;\n\t"
        "WD_%=:\n\t}"
        :: "r"(mbar), "r"(parity) : "memory");
}
__device__ __forceinline__ void mma_e4m3(float* d, const uint32_t* a, const uint32_t* b) {
    asm volatile(
        "mma.sync.aligned.m16n8k32.row.col.f32.e4m3.e4m3.f32 "
        "{%0,%1,%2,%3}, {%4,%5,%6,%7}, {%8,%9}, {%0,%1,%2,%3};"
        : "+f"(d[0]), "+f"(d[1]), "+f"(d[2]), "+f"(d[3])
        : "r"(a[0]), "r"(a[1]), "r"(a[2]), "r"(a[3]), "r"(b[0]), "r"(b[1]));
}
__device__ __forceinline__ uint32_t smem_u32(const void* p) {
    uint32_t a;
    asm("{ .reg .u64 t; cvta.to.shared.u64 t, %1; cvt.u32.u64 %0, t; }" : "=r"(a) : "l"(p));
    return a;
}

// ---------------- kernel 2: fp8 mma GEMM (PDL, waits on segment flag) --------
__global__ __launch_bounds__(256, 2) void gemm_kernel() {
    extern __shared__ uint8_t sh[];
    const uint32_t smem_base = smem_u32(sh);

    const int bn    = blockIdx.x * BN;
    const int bm    = blockIdx.y * BM;
    const int split = blockIdx.z;
    const int kc0   = split * NIT;
    const int tid   = threadIdx.x;
    const int warp  = tid >> 5;
    const int lane  = tid & 31;
    const int q     = lane >> 2;
    const int r4    = (lane & 3) * 4;
    const int wm    = (warp & 3) * 32;
    const int wn    = (warp >> 2) * 64;

    // wait until prep finished this K-segment (all PREP_CTAS counted)
    if (tid == 0) {
        volatile int* f = g_flags + split;
        while (*f < PREP_CTAS) __nanosleep(200);
    }
    __syncthreads();
    __threadfence();

    const uint8_t* Asrc = g_AB + (size_t)(bm >> 7) * NKC * BLK;
    const uint8_t* Bsrc = g_WB + (size_t)(bn >> 7) * NKC * BLK;

    float acc[2][8][4];
    #pragma unroll
    for (int i = 0; i < 2; ++i)
        #pragma unroll
        for (int j = 0; j < 8; ++j)
            #pragma unroll
            for (int e = 0; e < 4; ++e)
                acc[i][j][e] = 0.0f;

    if (tid == 0) {
        #pragma unroll
        for (int s = 0; s < STAGES; ++s) mbar_init(smem_base + 8 * s, 1);
    }
    __syncthreads();

    if (tid == 0) {
        #pragma unroll
        for (int s = 0; s < STAGES; ++s) {
            const uint32_t mb = smem_base + 8 * s;
            const uint32_t sd = smem_base + SMEM_DATA + s * STAGE_BYTES;
            mbar_expect_tx(mb, STAGE_BYTES);
            bulk_ld(sd,       Asrc + (size_t)(kc0 + s) * BLK, BLK, mb);
            bulk_ld(sd + BLK, Bsrc + (size_t)(kc0 + s) * BLK, BLK, mb);
        }
    }

    for (int it = 0; it < NIT; ++it) {
        const int s = it % STAGES;
        mbar_wait(smem_base + 8 * s, (uint32_t)((it / STAGES) & 1));

        const uint8_t* As = sh + SMEM_DATA + s * STAGE_BYTES;
        const uint8_t* Bs = As + BLK;
        const uint32_t qk = (uint32_t)(q << 4);

        #pragma unroll
        for (int ks = 0; ks < 4; ++ks) {
            const uint32_t k0 = ((uint32_t)(ks * 32 + r4)) ^ qk;
            const uint32_t k1 = k0 ^ 16u;
            uint32_t a[2][4], b[8][2];
            #pragma unroll
            for (int i = 0; i < 2; ++i) {
                const uint8_t* p0 = As + ((wm + i * 16 + q) << 7);
                const uint8_t* p1 = p0 + (8 << 7);
                a[i][0] = *(const uint32_t*)(p0 + k0);
                a[i][1] = *(const uint32_t*)(p1 + k0);
                a[i][2] = *(const uint32_t*)(p0 + k1);
                a[i][3] = *(const uint32_t*)(p1 + k1);
            }
            #pragma unroll
            for (int j = 0; j < 8; ++j) {
                const uint8_t* nb = Bs + ((wn + j * 8 + q) << 7);
                b[j][0] = *(const uint32_t*)(nb + k0);
                b[j][1] = *(const uint32_t*)(nb + k1);
            }
            #pragma unroll
            for (int i = 0; i < 2; ++i)
                #pragma unroll
                for (int j = 0; j < 8; ++j)
                    mma_e4m3(acc[i][j], a[i], b[j]);
        }

        __syncthreads();
        if (tid == 0 && it + STAGES < NIT) {
            const uint32_t mb = smem_base + 8 * s;
            const uint32_t sd = smem_base + SMEM_DATA + s * STAGE_BYTES;
            mbar_expect_tx(mb, STAGE_BYTES);
            bulk_ld(sd,       Asrc + (size_t)(kc0 + it + STAGES) * BLK, BLK, mb);
            bulk_ld(sd + BLK, Bsrc + (size_t)(kc0 + it + STAGES) * BLK, BLK, mb);
        }
    }

    float* base = g_part + (size_t)split * M_ * NPAD;
    #pragma unroll
    for (int i = 0; i < 2; ++i) {
        const int row0 = bm + wm + i * 16 + q;
        #pragma unroll
        for (int j = 0; j < 8; ++j) {
            const int col = bn + wn + j * 8 + (lane & 3) * 2;
            *(float2*)(base + (size_t)row0 * NPAD + col)       = make_float2(acc[i][j][0], acc[i][j][1]);
            *(float2*)(base + (size_t)(row0 + 8) * NPAD + col) = make_float2(acc[i][j][2], acc[i][j][3]);
        }
    }
}

// ---------------- kernel 3: reduce + NLL + (last block) final mean --------
__global__ __launch_bounds__(256) void nll_kernel(const float* __restrict__ bias,
                                                  const int* __restrict__ labels,
                                                  float* __restrict__ out) {
    const int m = blockIdx.x;
    const int tid = threadIdx.x;
    const int lbl = labels[m];

    __shared__ float row[NPAD];
    __shared__ float red[256];
    __shared__ int   amLast;

    for (int c = tid; c < C_; c += 256) {
        float v = 0.0f;
        #pragma unroll
        for (int s = 0; s < SPLITS; ++s)
            v += g_part[(size_t)s * M_ * NPAD + (size_t)m * NPAD + c];
        row[c] = v * INV_SCALE + bias[c];
    }
    __syncthreads();

    float mx = -INFINITY;
    for (int c = tid; c < C_; c += 256) mx = fmaxf(mx, row[c]);
    red[tid] = mx;
    __syncthreads();
    for (int s = 128; s > 0; s >>= 1) {
        if (tid < s) red[tid] = fmaxf(red[tid], red[tid + s]);
        __syncthreads();
    }
    const float smax = red[0];
    __syncthreads();

    float sum = 0.0f;
    for (int c = tid; c < C_; c += 256) sum += __expf(row[c] - smax);
    red[tid] = sum;
    __syncthreads();
    for (int s = 128; s > 0; s >>= 1) {
        if (tid < s) red[tid] += red[tid + s];
        __syncthreads();
    }

    if (tid == 0) {
        if (lbl >= 0) {
            g_row_nll[m] = logf(red[0]) + smax - row[lbl];
            g_row_valid[m] = 1;
        } else {
            g_row_nll[m] = 0.0f;
            g_row_valid[m] = 0;
        }
        __threadfence();
        amLast = (atomicAdd(&g_flags[7], 1) == M_ - 1);
    }
    __syncthreads();

    if (amLast) {
        __shared__ int scnt[256];
        float s = 0.0f; int c = 0;
        for (int i = tid; i < M_; i += 256) { s += g_row_nll[i]; c += g_row_valid[i]; }
        red[tid] = s; scnt[tid] = c;
        __syncthreads();
        for (int st = 128; st > 0; st >>= 1) {
            if (tid < st) { red[tid] += red[tid + st]; scnt[tid] += scnt[tid + st]; }
            __syncthreads();
        }
        if (tid == 0) {
            int n = scnt[0] > 0 ? scnt[0] : 1;
            out[0] = red[0] / (float)n;
        }
    }
}

// ---------------- launch: PDL overlap, single stream, no allocations --------
extern "C" void kernel_launch(void* const* d_in, const int* in_sizes, int n_in,
                              void* d_out, int out_size) {
    const float* feats  = (const float*)d_in[0];
    const float* Wmat   = (const float*)d_in[1];
    const float* bias   = (const float*)d_in[2];
    const int*   target = (const int*)d_in[4];
    const int*   lens   = (const int*)d_in[5];

    cudaFuncSetAttribute(gemm_kernel, cudaFuncAttributeMaxDynamicSharedMemorySize, SMEM_TOTAL);

    // reset flags (segment counters + nll counter)
    void* flags_addr = nullptr;
    cudaGetSymbolAddress(&flags_addr, g_flags);
    cudaMemsetAsync(flags_addr, 0, 8 * sizeof(int), 0);

    // 1) persistent prep (triggers PDL completion at CTA start)
    prep_kernel<<<PREP_CTAS, 256>>>(feats, lens, Wmat);

    // 2) gemm launched with programmatic stream serialization -> overlaps prep
    {
        cudaLaunchConfig_t cfg = {};
        cfg.gridDim  = dim3(NPAD / BN, M_ / BM, SPLITS);   // (8, 8, 7)
        cfg.blockDim = dim3(256, 1, 1);
        cfg.dynamicSmemBytes = SMEM_TOTAL;
        cfg.stream = 0;
        cudaLaunchAttribute attrs[1];
        attrs[0].id = cudaLaunchAttributeProgrammaticStreamSerialization;
        attrs[0].val.programmaticStreamSerializationAllowed = 1;
        cfg.attrs = attrs;
        cfg.numAttrs = 1;
        cudaLaunchKernelEx(&cfg, gemm_kernel);
    }

    // 3) NLL + fused final mean (normal full dependency on gemm)
    nll_kernel<<<M_, 256>>>(bias, target, (float*)d_out);
}

// round 15
// speedup vs baseline: 1.0490x; 1.0490x over previous
#include <cuda_runtime.h>
#include <cuda_bf16.h>
#include <cuda_fp8.h>
#include <math.h>
#include <cstdint>
#include <cstddef>

// Problem constants
#define B_    16
#define NT_   64
#define T_    8
#define D_    25088
#define C_    1000
#define M_    (B_ * NT_)   // 1024
#define NPAD  1024
#define K_    D_

// FP8 scaling
#define SCALE_A  64.0f
#define SCALE_W  2048.0f
#define INV_SCALE (1.0f / (SCALE_A * SCALE_W))

// GEMM tiling (fp8 mma.sync m16n8k32) + bulk-copy pipeline
#define BM     128
#define BN     128
#define BKK    128             // fp8 elems (bytes) per K-chunk
#define STAGES 3
#define SPLITS 7
#define NKC    (K_ / BKK)      // 196 chunks total
#define NIT    (NKC / SPLITS)  // 28 chunks per split
#define SEGW   896             // words (float4) per row per segment = 28 chunks
#define BLK    16384           // one [128 rows x 128 B] block
#define STAGE_BYTES (2 * BLK)
#define SMEM_DATA   1024
#define SMEM_TOTAL  (SMEM_DATA + STAGES * STAGE_BYTES)   // 99328

#define PREP_CTAS 888          // 6 CTAs/SM -> 48 warps; +16 gemm warps = 64 cap
#define NJOBS     2048         // 1024 pool rows + 1024 W rows

// ---------------- scratch (blocked, pre-swizzled fp8) ----------------
__device__ __align__(1024) uint8_t g_AB[(size_t)(M_ / 128) * NKC * BLK];
__device__ __align__(1024) uint8_t g_WB[(size_t)(NPAD / 128) * NKC * BLK];
__device__ float g_part[(size_t)SPLITS * M_ * NPAD];
__device__ float g_row_nll[M_];
__device__ int   g_row_valid[M_];
__device__ int   g_flags[8];   // [0..6] segment-done counters, [7] nll done count

__device__ __forceinline__ uint8_t to_e4m3(float v) {
    return (uint8_t)__nv_cvt_float_to_fp8(v, __NV_SATFINITE, __NV_E4M3);
}

// ---------------- kernel 1: persistent prep, 7 K-segments, flags ----------------
__global__ __launch_bounds__(256) void prep_kernel(const float* __restrict__ feats,
                                                   const int* __restrict__ lens,
                                                   const float* __restrict__ W) {
#if __CUDA_ARCH__ >= 900
    if (threadIdx.x == 0) cudaTriggerProgrammaticLaunchCompletion();
#endif
    for (int seg = 0; seg < SPLITS; ++seg) {
        const int wbeg = seg * SEGW;
        const int wend = wbeg + SEGW;
        for (int job = blockIdx.x; job < NJOBS; job += PREP_CTAS) {
            if (job < M_) {
                const int m = job;
                const int b = m / NT_;
                const int len = lens[b];
                const float inv = SCALE_A / (float)len;
                const float4* base = (const float4*)(feats + (size_t)m * T_ * D_);
                const int row = m & 127;
                const int mt  = m >> 7;
                const uint32_t rkey = (uint32_t)((row & 7) << 4);
                uint8_t* tile0 = g_AB + (size_t)mt * NKC * BLK;

                for (int i = wbeg + threadIdx.x; i < wend; i += blockDim.x) {
                    float4 acc = make_float4(0.f, 0.f, 0.f, 0.f);
                    #pragma unroll
                    for (int t = 0; t < T_; ++t) {
                        if (t < len) {
                            float4 v = __ldcs(base + (size_t)t * (D_ / 4) + i);
                            acc.x += v.x; acc.y += v.y; acc.z += v.z; acc.w += v.w;
                        }
                    }
                    uchar4 o;
                    o.x = to_e4m3(acc.x * inv);
                    o.y = to_e4m3(acc.y * inv);
                    o.z = to_e4m3(acc.z * inv);
                    o.w = to_e4m3(acc.w * inv);
                    const int kc  = i >> 5;
                    const int bby = (i & 31) * 4;
                    uint8_t* dst = tile0 + (size_t)kc * BLK + (row << 7) + ((uint32_t)bby ^ rkey);
                    *(uchar4*)dst = o;
                }
            } else {
                const int n = job - M_;        // 0..1023 incl. zero pad rows
                const int row = n & 127;
                const int nt  = n >> 7;
                const uint32_t rkey = (uint32_t)((row & 7) << 4);
                uint8_t* tile0 = g_WB + (size_t)nt * NKC * BLK;
                const int valid = (n < C_);
                const float4* src = (const float4*)(W + (size_t)(valid ? n : 0) * K_);

                for (int i = wbeg + threadIdx.x; i < wend; i += blockDim.x) {
                    uchar4 o = make_uchar4(0, 0, 0, 0);
                    if (valid) {
                        float4 v = __ldcs(src + i);
                        o.x = to_e4m3(v.x * SCALE_W);
                        o.y = to_e4m3(v.y * SCALE_W);
                        o.z = to_e4m3(v.z * SCALE_W);
                        o.w = to_e4m3(v.w * SCALE_W);
                    }
                    const int kc  = i >> 5;
                    const int bby = (i & 31) * 4;
                    uint8_t* dst = tile0 + (size_t)kc * BLK + (row << 7) + ((uint32_t)bby ^ rkey);
                    *(uchar4*)dst = o;
                }
            }
        }
        __syncthreads();
        if (threadIdx.x == 0) {
            __threadfence();
            atomicAdd(&g_flags[seg], 1);
        }
    }
}

// ---------------- bulk copy + mbarrier helpers ----------------
__device__ __forceinline__ void bulk_ld(uint32_t smem_dst, const void* gsrc,
                                        uint32_t bytes, uint32_t mbar) {
    asm volatile(
        "cp.async.bulk.shared::cluster.global.mbarrier::complete_tx::bytes [%0], [%1], %2, [%3];"
        :: "r"(smem_dst), "l"(gsrc), "r"(bytes), "r"(mbar) : "memory");
}
__device__ __forceinline__ void mbar_init(uint32_t mbar, uint32_t cnt) {
    asm volatile("mbarrier.init.shared.b64 [%0], %1;" :: "r"(mbar), "r"(cnt) : "memory");
}
__device__ __forceinline__ void mbar_expect_tx(uint32_t mbar, uint32_t bytes) {
    asm volatile("mbarrier.arrive.expect_tx.shared.b64 _, [%0], %1;"
                 :: "r"(mbar), "r"(bytes) : "memory");
}
__device__ __forceinline__ void mbar_wait(uint32_t mbar, uint32_t parity) {
    asm volatile(
        "{\n\t.reg .pred P1;\n\t"
        "WL_%=:\n\t"
        "mbarrier.try_wait.parity.acquire.cta.shared::cta.b64 P1, [%0], %1, 0x989680;\n\t"
        "@P1 bra.uni WD_%=;\n\t"
        "bra.uni WL_%=;\n\t"
        "WD_%=:\n\t}"
        :: "r"(mbar), "r"(parity) : "memory");
}
__device__ __forceinline__ void mma_e4m3(float* d, const uint32_t* a, const uint32_t* b) {
    asm volatile(
        "mma.sync.aligned.m16n8k32.row.col.f32.e4m3.e4m3.f32 "
        "{%0,%1,%2,%3}, {%4,%5,%6,%7}, {%8,%9}, {%0,%1,%2,%3};"
        : "+f"(d[0]), "+f"(d[1]), "+f"(d[2]), "+f"(d[3])
        : "r"(a[0]), "r"(a[1]), "r"(a[2]), "r"(a[3]), "r"(b[0]), "r"(b[1]));
}
__device__ __forceinline__ uint32_t smem_u32(const void* p) {
    uint32_t a;
    asm("{ .reg .u64 t; cvta.to.shared.u64 t, %1; cvt.u32.u64 %0, t; }" : "=r"(a) : "l"(p));
    return a;
}

// ---------------- kernel 2: fp8 mma GEMM (PDL, waits on segment flag) --------
__global__ __launch_bounds__(256, 2) void gemm_kernel() {
    extern __shared__ uint8_t sh[];
    const uint32_t smem_base = smem_u32(sh);

    const int bn    = blockIdx.x * BN;
    const int bm    = blockIdx.y * BM;
    const int split = blockIdx.z;
    const int kc0   = split * NIT;
    const int tid   = threadIdx.x;
    const int warp  = tid >> 5;
    const int lane  = tid & 31;
    const int q     = lane >> 2;
    const int r4    = (lane & 3) * 4;
    const int wm    = (warp & 3) * 32;
    const int wn    = (warp >> 2) * 64;

    // wait until prep finished this K-segment (all PREP_CTAS counted)
    if (tid == 0) {
        volatile int* f = g_flags + split;
        while (*f < PREP_CTAS) __nanosleep(200);
    }
    __syncthreads();
    __threadfence();

    const uint8_t* Asrc = g_AB + (size_t)(bm >> 7) * NKC * BLK;
    const uint8_t* Bsrc = g_WB + (size_t)(bn >> 7) * NKC * BLK;

    float acc[2][8][4];
    #pragma unroll
    for (int i = 0; i < 2; ++i)
        #pragma unroll
        for (int j = 0; j < 8; ++j)
            #pragma unroll
            for (int e = 0; e < 4; ++e)
                acc[i][j][e] = 0.0f;

    if (tid == 0) {
        #pragma unroll
        for (int s = 0; s < STAGES; ++s) mbar_init(smem_base + 8 * s, 1);
    }
    __syncthreads();

    if (tid == 0) {
        #pragma unroll
        for (int s = 0; s < STAGES; ++s) {
            const uint32_t mb = smem_base + 8 * s;
            const uint32_t sd = smem_base + SMEM_DATA + s * STAGE_BYTES;
            mbar_expect_tx(mb, STAGE_BYTES);
            bulk_ld(sd,       Asrc + (size_t)(kc0 + s) * BLK, BLK, mb);
            bulk_ld(sd + BLK, Bsrc + (size_t)(kc0 + s) * BLK, BLK, mb);
        }
    }

    for (int it = 0; it < NIT; ++it) {
        const int s = it % STAGES;
        mbar_wait(smem_base + 8 * s, (uint32_t)((it / STAGES) & 1));

        const uint8_t* As = sh + SMEM_DATA + s * STAGE_BYTES;
        const uint8_t* Bs = As + BLK;
        const uint32_t qk = (uint32_t)(q << 4);

        #pragma unroll
        for (int ks = 0; ks < 4; ++ks) {
            const uint32_t k0 = ((uint32_t)(ks * 32 + r4)) ^ qk;
            const uint32_t k1 = k0 ^ 16u;
            uint32_t a[2][4], b[8][2];
            #pragma unroll
            for (int i = 0; i < 2; ++i) {
                const uint8_t* p0 = As + ((wm + i * 16 + q) << 7);
                const uint8_t* p1 = p0 + (8 << 7);
                a[i][0] = *(const uint32_t*)(p0 + k0);
                a[i][1] = *(const uint32_t*)(p1 + k0);
                a[i][2] = *(const uint32_t*)(p0 + k1);
                a[i][3] = *(const uint32_t*)(p1 + k1);
            }
            #pragma unroll
            for (int j = 0; j < 8; ++j) {
                const uint8_t* nb = Bs + ((wn + j * 8 + q) << 7);
                b[j][0] = *(const uint32_t*)(nb + k0);
                b[j][1] = *(const uint32_t*)(nb + k1);
            }
            #pragma unroll
            for (int i = 0; i < 2; ++i)
                #pragma unroll
                for (int j = 0; j < 8; ++j)
                    mma_e4m3(acc[i][j], a[i], b[j]);
        }

        __syncthreads();
        if (tid == 0 && it + STAGES < NIT) {
            const uint32_t mb = smem_base + 8 * s;
            const uint32_t sd = smem_base + SMEM_DATA + s * STAGE_BYTES;
            mbar_expect_tx(mb, STAGE_BYTES);
            bulk_ld(sd,       Asrc + (size_t)(kc0 + it + STAGES) * BLK, BLK, mb);
            bulk_ld(sd + BLK, Bsrc + (size_t)(kc0 + it + STAGES) * BLK, BLK, mb);
        }
    }

    float* base = g_part + (size_t)split * M_ * NPAD;
    #pragma unroll
    for (int i = 0; i < 2; ++i) {
        const int row0 = bm + wm + i * 16 + q;
        #pragma unroll
        for (int j = 0; j < 8; ++j) {
            const int col = bn + wn + j * 8 + (lane & 3) * 2;
            *(float2*)(base + (size_t)row0 * NPAD + col)       = make_float2(acc[i][j][0], acc[i][j][1]);
            *(float2*)(base + (size_t)(row0 + 8) * NPAD + col) = make_float2(acc[i][j][2], acc[i][j][3]);
        }
    }
}

// ---------------- kernel 3: reduce + NLL + (last block) final mean --------
__global__ __launch_bounds__(256) void nll_kernel(const float* __restrict__ bias,
                                                  const int* __restrict__ labels,
                                                  float* __restrict__ out) {
    const int m = blockIdx.x;
    const int tid = threadIdx.x;
    const int lbl = labels[m];

    __shared__ float row[NPAD];
    __shared__ float red[256];
    __shared__ int   amLast;

    for (int c = tid; c < C_; c += 256) {
        float v = 0.0f;
        #pragma unroll
        for (int s = 0; s < SPLITS; ++s)
            v += g_part[(size_t)s * M_ * NPAD + (size_t)m * NPAD + c];
        row[c] = v * INV_SCALE + bias[c];
    }
    __syncthreads();

    float mx = -INFINITY;
    for (int c = tid; c < C_; c += 256) mx = fmaxf(mx, row[c]);
    red[tid] = mx;
    __syncthreads();
    for (int s = 128; s > 0; s >>= 1) {
        if (tid < s) red[tid] = fmaxf(red[tid], red[tid + s]);
        __syncthreads();
    }
    const float smax = red[0];
    __syncthreads();

    float sum = 0.0f;
    for (int c = tid; c < C_; c += 256) sum += __expf(row[c] - smax);
    red[tid] = sum;
    __syncthreads();
    for (int s = 128; s > 0; s >>= 1) {
        if (tid < s) red[tid] += red[tid + s];
        __syncthreads();
    }

    if (tid == 0) {
        if (lbl >= 0) {
            g_row_nll[m] = logf(red[0]) + smax - row[lbl];
            g_row_valid[m] = 1;
        } else {
            g_row_nll[m] = 0.0f;
            g_row_valid[m] = 0;
        }
        __threadfence();
        amLast = (atomicAdd(&g_flags[7], 1) == M_ - 1);
    }
    __syncthreads();

    if (amLast) {
        __shared__ int scnt[256];
        float s = 0.0f; int c = 0;
        for (int i = tid; i < M_; i += 256) { s += g_row_nll[i]; c += g_row_valid[i]; }
        red[tid] = s; scnt[tid] = c;
        __syncthreads();
        for (int st = 128; st > 0; st >>= 1) {
            if (tid < st) { red[tid] += red[tid + st]; scnt[tid] += scnt[tid + st]; }
            __syncthreads();
        }
        if (tid == 0) {
            int n = scnt[0] > 0 ? scnt[0] : 1;
            out[0] = red[0] / (float)n;
        }
    }
}

// ---------------- launch: PDL overlap, single stream, no allocations --------
extern "C" void kernel_launch(void* const* d_in, const int* in_sizes, int n_in,
                              void* d_out, int out_size) {
    const float* feats  = (const float*)d_in[0];
    const float* Wmat   = (const float*)d_in[1];
    const float* bias   = (const float*)d_in[2];
    const int*   target = (const int*)d_in[4];
    const int*   lens   = (const int*)d_in[5];

    cudaFuncSetAttribute(gemm_kernel, cudaFuncAttributeMaxDynamicSharedMemorySize, SMEM_TOTAL);

    // reset flags (segment counters + nll counter)
    void* flags_addr = nullptr;
    cudaGetSymbolAddress(&flags_addr, g_flags);
    cudaMemsetAsync(flags_addr, 0, 8 * sizeof(int), 0);

    // 1) persistent prep (triggers PDL completion at CTA start)
    prep_kernel<<<PREP_CTAS, 256>>>(feats, lens, Wmat);

    // 2) gemm launched with programmatic stream serialization -> overlaps prep
    {
        cudaLaunchConfig_t cfg = {};
        cfg.gridDim  = dim3(NPAD / BN, M_ / BM, SPLITS);   // (8, 8, 7)
        cfg.blockDim = dim3(256, 1, 1);
        cfg.dynamicSmemBytes = SMEM_TOTAL;
        cfg.stream = 0;
        cudaLaunchAttribute attrs[1];
        attrs[0].id = cudaLaunchAttributeProgrammaticStreamSerialization;
        attrs[0].val.programmaticStreamSerializationAllowed = 1;
        cfg.attrs = attrs;
        cfg.numAttrs = 1;
        cudaLaunchKernelEx(&cfg, gemm_kernel);
    }

    // 3) NLL + fused final mean (normal full dependency on gemm)
    nll_kernel<<<M_, 256>>>(bias, target, (float*)d_out);
}